// round 2
// baseline (speedup 1.0000x reference)
#include <cuda_runtime.h>
#include <math.h>

#define B_ 2
#define CIN_ 8
#define H_ 224
#define W_ 224
#define F_ 64
#define E_ 8
#define P_ 10
#define S_ 5
#define K_ 7
#define N1_ 43
#define N_ 1849          // N1_*N1_
#define M_ 49            // (2*WIN+1)^2
#define D_ 800           // E_*P_*P_ (== CIN_*P_*P_)

// ---------------- scratch (static device globals; no allocation) ----------------
__device__ float g_t1[B_*F_*H_*W_];        // 25.7 MB
__device__ float g_t2[B_*F_*H_*W_];        // 25.7 MB
__device__ float g_xe[B_*E_*H_*W_];        //  3.2 MB
__device__ float g_ltmap[B_*H_*W_];        //  0.4 MB
__device__ float g_pe[B_*N_*D_];           // 11.8 MB
__device__ float g_sq[B_*N_];
__device__ float g_ltm[B_*N_];
__device__ float g_nb[K_*B_*N_*D_];        // 82.8 MB

// ---------------- generic 3x3 SAME conv, fp32 direct ----------------
// block: 32x8 threads; tile 32x32 spatial, 4 rows per thread, 8 out-channels/block
__global__ void conv3x3_kernel(const float* __restrict__ in, const float* __restrict__ wgt,
                               const float* __restrict__ bias, float* __restrict__ out,
                               int Cin, int Cout, int relu)
{
    __shared__ float s_in[34][34];
    __shared__ float s_w[8][9];
    int b    = blockIdx.z;
    int ocg  = blockIdx.y;
    int tile = blockIdx.x;
    int tx = tile % 7, ty = tile / 7;
    int x0 = tx*32, y0 = ty*32;
    int lx = threadIdx.x, ly = threadIdx.y;
    int tid = ly*32 + lx;

    float acc[4][8];
    #pragma unroll
    for (int p=0;p<4;p++)
        #pragma unroll
        for (int o=0;o<8;o++) acc[p][o]=0.f;

    for (int ic=0; ic<Cin; ic++){
        const float* inp = in + ((size_t)(b*Cin + ic))*H_*W_;
        for (int i=tid; i<34*34; i+=256){
            int r = i/34, c = i%34;
            int gr = y0-1+r, gc = x0-1+c;
            float v = 0.f;
            if (gr>=0 && gr<H_ && gc>=0 && gc<W_) v = inp[gr*W_+gc];
            s_in[r][c] = v;
        }
        if (tid < 72){
            int o = tid/9, kk = tid%9;
            int oc = ocg*8+o;
            s_w[o][kk] = (oc<Cout) ? wgt[(oc*Cin+ic)*9 + kk] : 0.f;
        }
        __syncthreads();

        float vv[4][9];
        #pragma unroll
        for (int p=0;p<4;p++)
            #pragma unroll
            for (int dr=0;dr<3;dr++)
                #pragma unroll
                for (int dc=0;dc<3;dc++)
                    vv[p][dr*3+dc] = s_in[ly + p*8 + dr][lx + dc];

        #pragma unroll
        for (int o=0;o<8;o++){
            #pragma unroll
            for (int kk=0;kk<9;kk++){
                float wv = s_w[o][kk];
                #pragma unroll
                for (int p=0;p<4;p++)
                    acc[p][o] = fmaf(vv[p][kk], wv, acc[p][o]);
            }
        }
        __syncthreads();
    }

    #pragma unroll
    for (int o=0;o<8;o++){
        int oc = ocg*8+o;
        if (oc<Cout){
            float bv = bias[oc];
            #pragma unroll
            for (int p=0;p<4;p++){
                float r = acc[p][o] + bv;
                if (relu) r = fmaxf(r, 0.f);
                out[((size_t)(b*Cout+oc)*H_ + (y0+ly+p*8))*W_ + x0+lx] = r;
            }
        }
    }
}

// ---------------- patch extraction: pe, ||pe||^2, mean log-temp ----------------
__global__ void patches_kernel()
{
    int bn = blockIdx.x;
    int b = bn / N_, n = bn % N_;
    int n1 = n / N1_, n2 = n % N1_;
    int r0 = n1*S_, c0 = n2*S_;
    int tid = threadIdx.x;   // 128

    float loc = 0.f;
    for (int d=tid; d<D_; d+=128){
        int c = d/100, rem = d%100, p1 = rem/10, p2 = rem%10;
        float v = g_xe[((b*E_+c)*H_ + r0+p1)*W_ + c0+p2];
        g_pe[(size_t)bn*D_ + d] = v;
        loc += v*v;
    }
    float lv = 0.f;
    if (tid < 100){
        int p1 = tid/10, p2 = tid%10;
        lv = g_ltmap[(b*H_ + r0+p1)*W_ + c0+p2];
    }
    __shared__ float r1s[4], r2s[4];
    int lane = tid & 31, wid = tid >> 5;
    #pragma unroll
    for (int off=16; off; off>>=1){
        loc += __shfl_xor_sync(0xffffffffu, loc, off);
        lv  += __shfl_xor_sync(0xffffffffu, lv,  off);
    }
    if (lane==0){ r1s[wid]=loc; r2s[wid]=lv; }
    __syncthreads();
    if (tid==0){
        g_sq[bn]  = r1s[0]+r1s[1]+r1s[2]+r1s[3];
        g_ltm[bn] = (r2s[0]+r2s[1]+r2s[2]+r2s[3]) * (1.f/100.f);
    }
}

// ------- fused: distances -> logits -> K iterative softmax -> aggregation -------
// one block (256 threads) per (b, query n)
__global__ void nnblock_kernel(const float* __restrict__ x)
{
    __shared__ float s_q[D_];
    __shared__ float s_logit[M_];
    __shared__ float s_wk[M_*K_];
    __shared__ int   s_c1[M_], s_c2[M_];

    int bn = blockIdx.x;
    int b = bn / N_, n = bn % N_;
    int q1 = n / N1_, q2 = n % N1_;
    int tid = threadIdx.x;

    if (tid < M_){
        int i = tid/7, j = tid%7;
        int c1 = min(max(q1+i-3,0), N1_-1);
        int c2 = min(max(q2+j-3,0), N1_-1);
        s_c1[tid]=c1; s_c2[tid]=c2;
    }
    for (int d=tid; d<D_; d+=256) s_q[d] = g_pe[(size_t)bn*D_ + d];
    __syncthreads();

    float sq_q  = g_sq[bn];
    float scale = expf(-g_ltm[bn]);
    int wid = tid>>5, lane = tid&31;

    // distances: each warp handles candidates m = wid, wid+8, ...
    for (int m=wid; m<M_; m+=8){
        int cand = s_c1[m]*N1_ + s_c2[m];
        const float* pc = g_pe + (size_t)(b*N_+cand)*D_;
        float s = 0.f;
        for (int j=lane; j<D_; j+=32) s += s_q[j]*pc[j];
        #pragma unroll
        for (int off=16; off; off>>=1) s += __shfl_xor_sync(0xffffffffu, s, off);
        if (lane==0){
            float Dv = -(sq_q + g_sq[b*N_+cand] - 2.f*s);
            s_logit[m] = (cand==n) ? -1e9f : Dv*scale;
        }
    }
    __syncthreads();

    // K=7 iterative softmax over 49 logits, done by warp 0 (2 values/lane)
    if (tid < 32){
        float a = s_logit[tid];
        bool hasb = (tid+32) < M_;
        float bvl = hasb ? s_logit[tid+32] : -INFINITY;
        #pragma unroll
        for (int k=0;k<K_;k++){
            float mx = fmaxf(a, bvl);
            #pragma unroll
            for (int off=16; off; off>>=1) mx = fmaxf(mx, __shfl_xor_sync(0xffffffffu, mx, off));
            float ea = expf(a - mx);
            float eb = hasb ? expf(bvl - mx) : 0.f;
            float ssum = ea + eb;
            #pragma unroll
            for (int off=16; off; off>>=1) ssum += __shfl_xor_sync(0xffffffffu, ssum, off);
            float inv = 1.f/ssum;
            float wa = ea*inv, wb = eb*inv;
            s_wk[tid*K_+k] = wa;
            if (hasb) s_wk[(tid+32)*K_+k] = wb;
            a   += log1pf(-fminf(wa, 1.f-1e-6f));
            bvl += log1pf(-fminf(wb, 1.f-1e-6f));
        }
    }
    __syncthreads();

    // aggregation: nb[k,b,n,d] = sum_m Wk[m,k] * x_patch(cand_m, d)
    for (int d=tid; d<D_; d+=256){
        int c = d/100, rem = d%100, p1 = rem/10, p2 = rem%10;
        float acc[K_];
        #pragma unroll
        for (int k=0;k<K_;k++) acc[k]=0.f;
        for (int m=0;m<M_;m++){
            float v = x[((b*CIN_+c)*H_ + s_c1[m]*S_+p1)*W_ + s_c2[m]*S_+p2];
            #pragma unroll
            for (int k=0;k<K_;k++) acc[k] = fmaf(s_wk[m*K_+k], v, acc[k]);
        }
        #pragma unroll
        for (int k=0;k<K_;k++)
            g_nb[((size_t)(k*B_+b)*N_ + n)*D_ + d] = acc[k];
    }
}

// ---------------- gather fold + x passthrough + normalization ----------------
__global__ void fold_kernel(const float* __restrict__ x, float* __restrict__ out)
{
    int idx = blockIdx.x*blockDim.x + threadIdx.x;
    const int total = B_*(K_+1)*CIN_*H_*W_;
    if (idx >= total) return;
    int w  = idx % W_;
    int r  = (idx / W_) % H_;
    int ch = (idx / (H_*W_)) % ((K_+1)*CIN_);
    int b  = idx / (H_*W_*(K_+1)*CIN_);

    if (ch < CIN_){
        out[idx] = x[((b*CIN_+ch)*H_+r)*W_+w];
        return;
    }
    int k = (ch - CIN_) / CIN_;
    int c = (ch - CIN_) % CIN_;

    int n1lo = (r >= P_-1) ? (r-(P_-1)+S_-1)/S_ : 0;
    int n1hi = min(N1_-1, r/S_);
    int n2lo = (w >= P_-1) ? (w-(P_-1)+S_-1)/S_ : 0;
    int n2hi = min(N1_-1, w/S_);

    float sum = 0.f; int cnt = 0;
    for (int n1=n1lo; n1<=n1hi; n1++){
        int p1 = r - n1*S_;
        for (int n2=n2lo; n2<=n2hi; n2++){
            int p2 = w - n2*S_;
            sum += g_nb[((size_t)(k*B_+b)*N_ + n1*N1_+n2)*D_ + c*100 + p1*10 + p2];
            cnt++;
        }
    }
    out[idx] = (cnt > 0) ? sum/(float)cnt : 0.f;
}

// ---------------- launch ----------------
extern "C" void kernel_launch(void* const* d_in, const int* in_sizes, int n_in,
                              void* d_out, int out_size)
{
    const float* x   = (const float*)d_in[0];
    const float* w1e = (const float*)d_in[1];
    const float* b1e = (const float*)d_in[2];
    const float* w2e = (const float*)d_in[3];
    const float* b2e = (const float*)d_in[4];
    const float* w3e = (const float*)d_in[5];
    const float* b3e = (const float*)d_in[6];
    const float* w1t = (const float*)d_in[7];
    const float* b1t = (const float*)d_in[8];
    const float* w2t = (const float*)d_in[9];
    const float* b2t = (const float*)d_in[10];
    const float* w3t = (const float*)d_in[11];
    const float* b3t = (const float*)d_in[12];

    float *t1, *t2, *xe, *ltmap;
    cudaGetSymbolAddress((void**)&t1,    g_t1);
    cudaGetSymbolAddress((void**)&t2,    g_t2);
    cudaGetSymbolAddress((void**)&xe,    g_xe);
    cudaGetSymbolAddress((void**)&ltmap, g_ltmap);

    dim3 cb(32,8);
    // embedding CNN
    conv3x3_kernel<<<dim3(49,8,B_), cb>>>(x,  w1e, b1e, t1, CIN_, F_, 1);
    conv3x3_kernel<<<dim3(49,8,B_), cb>>>(t1, w2e, b2e, t2, F_,   F_, 1);
    conv3x3_kernel<<<dim3(49,1,B_), cb>>>(t2, w3e, b3e, xe, F_,   E_, 0);
    // temperature CNN
    conv3x3_kernel<<<dim3(49,8,B_), cb>>>(x,  w1t, b1t, t1, CIN_, F_, 1);
    conv3x3_kernel<<<dim3(49,8,B_), cb>>>(t1, w2t, b2t, t2, F_,   F_, 1);
    conv3x3_kernel<<<dim3(49,1,B_), cb>>>(t2, w3t, b3t, ltmap, F_, 1, 0);

    patches_kernel<<<B_*N_, 128>>>();
    nnblock_kernel<<<B_*N_, 256>>>(x);

    const int total = B_*(K_+1)*CIN_*H_*W_;
    fold_kernel<<<(total+255)/256, 256>>>(x, (float*)d_out);
}

// round 3
// speedup vs baseline: 1.2181x; 1.2181x over previous
#include <cuda_runtime.h>
#include <math.h>

#define B_ 2
#define CIN_ 8
#define H_ 224
#define W_ 224
#define F_ 64
#define E_ 8
#define P_ 10
#define S_ 5
#define K_ 7
#define N1_ 43
#define N_ 1849          // N1_*N1_
#define M_ 49            // (2*WIN+1)^2
#define D_ 800           // CIN_*P_*P_

// ---------------- scratch (static device globals; no allocation) ----------------
__device__ float g_t1e[B_*F_*H_*W_];
__device__ float g_t1t[B_*F_*H_*W_];
__device__ float g_t2e[B_*F_*H_*W_];
__device__ float g_t2t[B_*F_*H_*W_];
__device__ float g_xe[B_*E_*H_*W_];
__device__ float g_ltmap[B_*H_*W_];
__device__ float g_pe[B_*N_*D_];
__device__ float g_sq[B_*N_];
__device__ float g_ltm[B_*N_];
__device__ float g_nb[K_*B_*N_*D_];

// ---------------- dual-network 3x3 SAME conv, fp32 direct ----------------
// block: 32x8; tile 32x32, 4 rows/thread, 8 oc per block. blockIdx.y selects
// oc-group; groups [0,gA) belong to network A, the rest to network B.
__global__ void __launch_bounds__(256, 4) conv3x3_dual(
    const float* __restrict__ inA, const float* __restrict__ wA,
    const float* __restrict__ bA, float* __restrict__ outA, int CoutA,
    const float* __restrict__ inB, const float* __restrict__ wB,
    const float* __restrict__ bB, float* __restrict__ outB, int CoutB,
    int Cin, int relu, int gA)
{
    __shared__ float s_in[34][34];
    __shared__ float s_w[8][9];
    int b   = blockIdx.z;
    int ocg = blockIdx.y;
    const float* in; const float* wgt; const float* bias; float* out; int Cout;
    if (ocg < gA){ in=inA; wgt=wA; bias=bA; out=outA; Cout=CoutA; }
    else { ocg -= gA; in=inB; wgt=wB; bias=bB; out=outB; Cout=CoutB; }

    int tile = blockIdx.x;
    int tx = tile % 7, ty = tile / 7;
    int x0 = tx*32, y0 = ty*32;
    int lx = threadIdx.x, ly = threadIdx.y;
    int tid = ly*32 + lx;

    float acc[4][8];
    #pragma unroll
    for (int p=0;p<4;p++)
        #pragma unroll
        for (int o=0;o<8;o++) acc[p][o]=0.f;

    for (int ic=0; ic<Cin; ic++){
        const float* inp = in + ((size_t)(b*Cin + ic))*H_*W_;
        for (int i=tid; i<34*34; i+=256){
            int r = i/34, c = i%34;
            int gr = y0-1+r, gc = x0-1+c;
            float v = 0.f;
            if (gr>=0 && gr<H_ && gc>=0 && gc<W_) v = inp[gr*W_+gc];
            s_in[r][c] = v;
        }
        if (tid < 72){
            int o = tid/9, kk = tid%9;
            int oc = ocg*8+o;
            s_w[o][kk] = (oc<Cout) ? wgt[(oc*Cin+ic)*9 + kk] : 0.f;
        }
        __syncthreads();

        #pragma unroll
        for (int dr=0;dr<3;dr++){
            #pragma unroll
            for (int dc=0;dc<3;dc++){
                float v0 = s_in[ly     +dr][lx+dc];
                float v1 = s_in[ly+ 8  +dr][lx+dc];
                float v2 = s_in[ly+16  +dr][lx+dc];
                float v3 = s_in[ly+24  +dr][lx+dc];
                int kk = dr*3+dc;
                #pragma unroll
                for (int o=0;o<8;o++){
                    float wv = s_w[o][kk];
                    acc[0][o] = fmaf(v0, wv, acc[0][o]);
                    acc[1][o] = fmaf(v1, wv, acc[1][o]);
                    acc[2][o] = fmaf(v2, wv, acc[2][o]);
                    acc[3][o] = fmaf(v3, wv, acc[3][o]);
                }
            }
        }
        __syncthreads();
    }

    #pragma unroll
    for (int o=0;o<8;o++){
        int oc = ocg*8+o;
        if (oc<Cout){
            float bv = bias[oc];
            #pragma unroll
            for (int p=0;p<4;p++){
                float r = acc[p][o] + bv;
                if (relu) r = fmaxf(r, 0.f);
                out[((size_t)(b*Cout+oc)*H_ + (y0+ly+p*8))*W_ + x0+lx] = r;
            }
        }
    }
}

// ---------------- patch extraction: pe, ||pe||^2, mean log-temp ----------------
__global__ void patches_kernel()
{
    int bn = blockIdx.x;
    int b = bn / N_, n = bn % N_;
    int n1 = n / N1_, n2 = n % N1_;
    int r0 = n1*S_, c0 = n2*S_;
    int tid = threadIdx.x;   // 128

    float loc = 0.f;
    for (int d=tid; d<D_; d+=128){
        int c = d/100, rem = d%100, p1 = rem/10, p2 = rem%10;
        float v = g_xe[((b*E_+c)*H_ + r0+p1)*W_ + c0+p2];
        g_pe[(size_t)bn*D_ + d] = v;
        loc += v*v;
    }
    float lv = 0.f;
    if (tid < 100){
        int p1 = tid/10, p2 = tid%10;
        lv = g_ltmap[(b*H_ + r0+p1)*W_ + c0+p2];
    }
    __shared__ float r1s[4], r2s[4];
    int lane = tid & 31, wid = tid >> 5;
    #pragma unroll
    for (int off=16; off; off>>=1){
        loc += __shfl_xor_sync(0xffffffffu, loc, off);
        lv  += __shfl_xor_sync(0xffffffffu, lv,  off);
    }
    if (lane==0){ r1s[wid]=loc; r2s[wid]=lv; }
    __syncthreads();
    if (tid==0){
        g_sq[bn]  = r1s[0]+r1s[1]+r1s[2]+r1s[3];
        g_ltm[bn] = (r2s[0]+r2s[1]+r2s[2]+r2s[3]) * (1.f/100.f);
    }
}

// ------- fused: distances -> logits -> K iterative softmax -> aggregation -------
// one block (256 threads) per (b, query n). Candidate-union x region staged in
// dynamic smem; aggregation is m-outer with register accumulators acc[4][7].
__global__ void __launch_bounds__(256) nnblock_kernel(const float* __restrict__ x)
{
    extern __shared__ float sm[];
    float* s_xf = sm;                 // 8 * 40 * 40 = 12800 floats
    float* s_q  = sm + 12800;         // 800 floats
    __shared__ float s_wk[M_][8];     // padded to 8 for float4 loads
    __shared__ float s_logit[M_];
    __shared__ int   s_cand[M_];
    __shared__ int   s_off[M_];

    int bn = blockIdx.x;
    int b = bn / N_, n = bn % N_;
    int q1 = n / N1_, q2 = n % N1_;
    int tid = threadIdx.x, lane = tid & 31, wid = tid >> 5;

    int c1lo = max(q1-3,0), c1hi = min(q1+3, N1_-1);
    int c2lo = max(q2-3,0), c2hi = min(q2+3, N1_-1);
    int rows = (c1hi-c1lo)*S_ + P_;   // <= 40
    int cols = (c2hi-c2lo)*S_ + P_;   // <= 40
    int r0 = c1lo*S_, c0 = c2lo*S_;

    if (tid < M_){
        int i = tid/7, j = tid%7;
        int c1 = min(max(q1+i-3,0), N1_-1);
        int c2 = min(max(q2+j-3,0), N1_-1);
        s_cand[tid] = c1*N1_ + c2;
        s_off[tid]  = ((c1-c1lo)*S_)*40 + (c2-c2lo)*S_;
    }
    for (int d=tid; d<D_; d+=256) s_q[d] = g_pe[(size_t)bn*D_ + d];

    // stage candidate-union x region: [8][rows][cols] stored with stride 40
    #pragma unroll
    for (int c=0;c<CIN_;c++){
        const float* src = x + ((size_t)(b*CIN_+c)*H_ + r0)*W_ + c0;
        for (int r=wid; r<rows; r+=8)
            for (int cc=lane; cc<cols; cc+=32)
                s_xf[c*1600 + r*40 + cc] = src[r*W_ + cc];
    }
    __syncthreads();

    float sq_q  = g_sq[bn];
    float scale = expf(-g_ltm[bn]);

    // distances from g_pe (coalesced rows, L2-resident)
    for (int m=wid; m<M_; m+=8){
        int cand = s_cand[m];
        const float* pc = g_pe + (size_t)(b*N_+cand)*D_;
        float s = 0.f;
        for (int j=lane; j<D_; j+=32) s += s_q[j]*pc[j];
        #pragma unroll
        for (int off=16; off; off>>=1) s += __shfl_xor_sync(0xffffffffu, s, off);
        if (lane==0){
            float Dv = -(sq_q + g_sq[b*N_+cand] - 2.f*s);
            s_logit[m] = (cand==n) ? -1e9f : Dv*scale;
        }
    }
    __syncthreads();

    // K=7 iterative softmax over 49 logits, warp 0 (2 values/lane)
    if (tid < 32){
        float a = s_logit[tid];
        bool hasb = (tid+32) < M_;
        float bvl = hasb ? s_logit[tid+32] : -INFINITY;
        #pragma unroll
        for (int k=0;k<K_;k++){
            float mx = fmaxf(a, bvl);
            #pragma unroll
            for (int off=16; off; off>>=1) mx = fmaxf(mx, __shfl_xor_sync(0xffffffffu, mx, off));
            float ea = expf(a - mx);
            float eb = hasb ? expf(bvl - mx) : 0.f;
            float ssum = ea + eb;
            #pragma unroll
            for (int off=16; off; off>>=1) ssum += __shfl_xor_sync(0xffffffffu, ssum, off);
            float inv = 1.f/ssum;
            float wa = ea*inv, wb = eb*inv;
            s_wk[tid][k] = wa;
            if (hasb) s_wk[tid+32][k] = wb;
            a   += log1pf(-fminf(wa, 1.f-1e-6f));
            bvl += log1pf(-fminf(wb, 1.f-1e-6f));
        }
    }
    __syncthreads();

    // aggregation: thread owns d = tid + 256*j (j=0..3), acc in registers
    int baseidx[4]; bool act[4];
    #pragma unroll
    for (int j=0;j<4;j++){
        int d = tid + 256*j;
        act[j] = (d < D_);
        int dd = act[j] ? d : 0;
        int c = dd/100, rem = dd%100, p1 = rem/10, p2 = rem%10;
        baseidx[j] = c*1600 + p1*40 + p2;
    }
    float acc[4][K_];
    #pragma unroll
    for (int j=0;j<4;j++)
        #pragma unroll
        for (int k=0;k<K_;k++) acc[j][k]=0.f;

    for (int m=0;m<M_;m++){
        int o = s_off[m];
        float4 w0 = *(const float4*)&s_wk[m][0];
        float4 w1 = *(const float4*)&s_wk[m][4];
        float v[4];
        #pragma unroll
        for (int j=0;j<4;j++) v[j] = s_xf[baseidx[j]+o];
        #pragma unroll
        for (int j=0;j<4;j++){
            acc[j][0] = fmaf(w0.x, v[j], acc[j][0]);
            acc[j][1] = fmaf(w0.y, v[j], acc[j][1]);
            acc[j][2] = fmaf(w0.z, v[j], acc[j][2]);
            acc[j][3] = fmaf(w0.w, v[j], acc[j][3]);
            acc[j][4] = fmaf(w1.x, v[j], acc[j][4]);
            acc[j][5] = fmaf(w1.y, v[j], acc[j][5]);
            acc[j][6] = fmaf(w1.z, v[j], acc[j][6]);
        }
    }
    #pragma unroll
    for (int j=0;j<4;j++){
        if (!act[j]) continue;
        int d = tid + 256*j;
        #pragma unroll
        for (int k=0;k<K_;k++)
            g_nb[((size_t)(k*B_+b)*N_ + n)*D_ + d] = acc[j][k];
    }
}

// ---------------- gather fold + x passthrough + normalization ----------------
__global__ void fold_kernel(const float* __restrict__ x, float* __restrict__ out)
{
    int idx = blockIdx.x*blockDim.x + threadIdx.x;
    const int total = B_*(K_+1)*CIN_*H_*W_;
    if (idx >= total) return;
    int w  = idx % W_;
    int r  = (idx / W_) % H_;
    int ch = (idx / (H_*W_)) % ((K_+1)*CIN_);
    int b  = idx / (H_*W_*(K_+1)*CIN_);

    if (ch < CIN_){
        out[idx] = x[((b*CIN_+ch)*H_+r)*W_+w];
        return;
    }
    int k = (ch - CIN_) / CIN_;
    int c = (ch - CIN_) % CIN_;

    int n1lo = (r >= P_-1) ? (r-(P_-1)+S_-1)/S_ : 0;
    int n1hi = min(N1_-1, r/S_);
    int n2lo = (w >= P_-1) ? (w-(P_-1)+S_-1)/S_ : 0;
    int n2hi = min(N1_-1, w/S_);

    float sum = 0.f; int cnt = 0;
    for (int n1=n1lo; n1<=n1hi; n1++){
        int p1 = r - n1*S_;
        for (int n2=n2lo; n2<=n2hi; n2++){
            int p2 = w - n2*S_;
            sum += g_nb[((size_t)(k*B_+b)*N_ + n1*N1_+n2)*D_ + c*100 + p1*10 + p2];
            cnt++;
        }
    }
    out[idx] = (cnt > 0) ? sum/(float)cnt : 0.f;
}

// ---------------- launch ----------------
extern "C" void kernel_launch(void* const* d_in, const int* in_sizes, int n_in,
                              void* d_out, int out_size)
{
    const float* x   = (const float*)d_in[0];
    const float* w1e = (const float*)d_in[1];
    const float* b1e = (const float*)d_in[2];
    const float* w2e = (const float*)d_in[3];
    const float* b2e = (const float*)d_in[4];
    const float* w3e = (const float*)d_in[5];
    const float* b3e = (const float*)d_in[6];
    const float* w1t = (const float*)d_in[7];
    const float* b1t = (const float*)d_in[8];
    const float* w2t = (const float*)d_in[9];
    const float* b2t = (const float*)d_in[10];
    const float* w3t = (const float*)d_in[11];
    const float* b3t = (const float*)d_in[12];

    float *t1e, *t1t, *t2e, *t2t, *xe, *ltmap;
    cudaGetSymbolAddress((void**)&t1e,   g_t1e);
    cudaGetSymbolAddress((void**)&t1t,   g_t1t);
    cudaGetSymbolAddress((void**)&t2e,   g_t2e);
    cudaGetSymbolAddress((void**)&t2t,   g_t2t);
    cudaGetSymbolAddress((void**)&xe,    g_xe);
    cudaGetSymbolAddress((void**)&ltmap, g_ltmap);

    static int attr_done = 0;
    if (!attr_done){
        cudaFuncSetAttribute(nnblock_kernel,
                             cudaFuncAttributeMaxDynamicSharedMemorySize, 56*1024);
        attr_done = 1;
    }

    dim3 cb(32,8);
    // layer 1: both networks, input x, 8+8 oc-groups
    conv3x3_dual<<<dim3(49,16,B_), cb>>>(x, w1e, b1e, t1e, F_,
                                         x, w1t, b1t, t1t, F_, CIN_, 1, 8);
    // layer 2
    conv3x3_dual<<<dim3(49,16,B_), cb>>>(t1e, w2e, b2e, t2e, F_,
                                         t1t, w2t, b2t, t2t, F_, F_, 1, 8);
    // layer 3: 8-ch embedding + 1-ch log-temp
    conv3x3_dual<<<dim3(49,2,B_), cb>>>(t2e, w3e, b3e, xe,    E_,
                                        t2t, w3t, b3t, ltmap, 1, F_, 0, 1);

    patches_kernel<<<B_*N_, 128>>>();
    nnblock_kernel<<<B_*N_, 256, (12800+800)*sizeof(float)>>>(x);

    const int total = B_*(K_+1)*CIN_*H_*W_;
    fold_kernel<<<(total+255)/256, 256>>>(x, (float*)d_out);
}

// round 4
// speedup vs baseline: 1.3212x; 1.0846x over previous
#include <cuda_runtime.h>
#include <math.h>

#define B_ 2
#define CIN_ 8
#define H_ 224
#define W_ 224
#define F_ 64
#define E_ 8
#define P_ 10
#define S_ 5
#define K_ 7
#define N1_ 43
#define N_ 1849          // N1_*N1_
#define M_ 49            // (2*WIN+1)^2
#define D_ 800           // CIN_*P_*P_

// ---------------- scratch (static device globals; no allocation) ----------------
__device__ float g_t1e[B_*F_*H_*W_];
__device__ float g_t1t[B_*F_*H_*W_];
__device__ float g_t2e[B_*F_*H_*W_];
__device__ float g_t2t[B_*F_*H_*W_];
__device__ float g_xe[B_*E_*H_*W_];
__device__ float g_ltmap[B_*H_*W_];
__device__ float g_pe[B_*N_*D_];
__device__ float g_sq[B_*N_];
__device__ float g_ltm[B_*N_];
__device__ float g_nb[K_*B_*N_*D_];

// =================================================================
// conv1 fused: layer-1 of BOTH networks, shared input x (Cin=8), relu.
// block 256, tile 32x32, acc[4][16]: o<8 -> net A oc0+o, o>=8 -> net B.
// double-buffered smem staging.
// =================================================================
__global__ void __launch_bounds__(256, 2) conv1_fused(
    const float* __restrict__ x,
    const float* __restrict__ wA, const float* __restrict__ bA, float* __restrict__ outA,
    const float* __restrict__ wB, const float* __restrict__ bB, float* __restrict__ outB)
{
    __shared__ float s_in[2][34*34];
    __shared__ float s_w[2][144];
    int b   = blockIdx.z;
    int oc0 = blockIdx.y * 8;
    int tile = blockIdx.x;
    int tx = tile % 7, ty = tile / 7;
    int x0 = tx*32, y0 = ty*32;
    int tid = threadIdx.x;
    int lx = tid & 31, ly = tid >> 5;

    int goff[5];
    #pragma unroll
    for (int j=0;j<5;j++){
        int i = tid + j*256;
        goff[j] = -1;
        if (i < 34*34){
            int r = i/34, c = i%34;
            int gr = y0-1+r, gc = x0-1+c;
            goff[j] = (gr>=0 && gr<H_ && gc>=0 && gc<W_) ? gr*W_+gc : -1;
        }
    }
    const float* inbase = x + (size_t)b*CIN_*H_*W_;
    const float* wp = wA;
    if (tid < 144){
        int o = tid/9, kk = tid%9;
        wp = (o < 8) ? (wA + ((oc0+o)*CIN_)*9 + kk)
                     : (wB + ((oc0+o-8)*CIN_)*9 + kk);
    }

    // stage ic = 0
    {
        const float* inp = inbase;
        #pragma unroll
        for (int j=0;j<5;j++){
            int i = tid + j*256;
            if (i < 34*34) s_in[0][i] = (goff[j] >= 0) ? inp[goff[j]] : 0.f;
        }
        if (tid < 144) s_w[0][tid] = wp[0];
    }
    __syncthreads();

    float acc[4][16];
    #pragma unroll
    for (int p=0;p<4;p++)
        #pragma unroll
        for (int o=0;o<16;o++) acc[p][o]=0.f;

    for (int ic=0; ic<CIN_; ic++){
        int buf = ic & 1;
        if (ic+1 < CIN_){
            const float* inp = inbase + (size_t)(ic+1)*H_*W_;
            int nb = buf^1;
            #pragma unroll
            for (int j=0;j<5;j++){
                int i = tid + j*256;
                if (i < 34*34) s_in[nb][i] = (goff[j] >= 0) ? inp[goff[j]] : 0.f;
            }
            if (tid < 144) s_w[nb][tid] = wp[(ic+1)*9];
        }
        const float* si = s_in[buf];
        const float* sw = s_w[buf];
        #pragma unroll
        for (int dr=0;dr<3;dr++){
            #pragma unroll
            for (int dc=0;dc<3;dc++){
                int kk = dr*3+dc;
                float v0 = si[(ly   +dr)*34 + lx+dc];
                float v1 = si[(ly+ 8+dr)*34 + lx+dc];
                float v2 = si[(ly+16+dr)*34 + lx+dc];
                float v3 = si[(ly+24+dr)*34 + lx+dc];
                #pragma unroll
                for (int o=0;o<16;o++){
                    float wv = sw[o*9+kk];
                    acc[0][o] = fmaf(v0,wv,acc[0][o]);
                    acc[1][o] = fmaf(v1,wv,acc[1][o]);
                    acc[2][o] = fmaf(v2,wv,acc[2][o]);
                    acc[3][o] = fmaf(v3,wv,acc[3][o]);
                }
            }
        }
        __syncthreads();
    }

    #pragma unroll
    for (int o=0;o<16;o++){
        int oc = oc0 + ((o<8) ? o : o-8);
        float bv = (o<8) ? bA[oc] : bB[oc];
        float* op = (o<8) ? outA : outB;
        #pragma unroll
        for (int p=0;p<4;p++){
            float r = fmaxf(acc[p][o] + bv, 0.f);
            op[((size_t)(b*F_+oc)*H_ + (y0+ly+p*8))*W_ + x0+lx] = r;
        }
    }
}

// =================================================================
// conv2: 64->64, relu. blockIdx.y<4 -> net A group y, else net B.
// 16 oc per block, double-buffered smem.
// =================================================================
__global__ void __launch_bounds__(256, 2) conv64x64(
    const float* __restrict__ inA, const float* __restrict__ wA,
    const float* __restrict__ bA, float* __restrict__ outA,
    const float* __restrict__ inB, const float* __restrict__ wB,
    const float* __restrict__ bB, float* __restrict__ outB)
{
    __shared__ float s_in[2][34*34];
    __shared__ float s_w[2][144];
    int b = blockIdx.z;
    int g = blockIdx.y;
    const float* in; const float* wgt; const float* bias; float* out;
    if (g < 4){ in=inA; wgt=wA; bias=bA; out=outA; }
    else { g -= 4; in=inB; wgt=wB; bias=bB; out=outB; }
    int oc0 = g*16;

    int tile = blockIdx.x;
    int tx = tile % 7, ty = tile / 7;
    int x0 = tx*32, y0 = ty*32;
    int tid = threadIdx.x;
    int lx = tid & 31, ly = tid >> 5;

    int goff[5];
    #pragma unroll
    for (int j=0;j<5;j++){
        int i = tid + j*256;
        goff[j] = -1;
        if (i < 34*34){
            int r = i/34, c = i%34;
            int gr = y0-1+r, gc = x0-1+c;
            goff[j] = (gr>=0 && gr<H_ && gc>=0 && gc<W_) ? gr*W_+gc : -1;
        }
    }
    const float* inbase = in + (size_t)b*F_*H_*W_;
    const float* wp = wgt;
    if (tid < 144){
        int o = tid/9, kk = tid%9;
        wp = wgt + ((oc0+o)*F_)*9 + kk;
    }

    {
        const float* inp = inbase;
        #pragma unroll
        for (int j=0;j<5;j++){
            int i = tid + j*256;
            if (i < 34*34) s_in[0][i] = (goff[j] >= 0) ? inp[goff[j]] : 0.f;
        }
        if (tid < 144) s_w[0][tid] = wp[0];
    }
    __syncthreads();

    float acc[4][16];
    #pragma unroll
    for (int p=0;p<4;p++)
        #pragma unroll
        for (int o=0;o<16;o++) acc[p][o]=0.f;

    for (int ic=0; ic<F_; ic++){
        int buf = ic & 1;
        if (ic+1 < F_){
            const float* inp = inbase + (size_t)(ic+1)*H_*W_;
            int nb = buf^1;
            #pragma unroll
            for (int j=0;j<5;j++){
                int i = tid + j*256;
                if (i < 34*34) s_in[nb][i] = (goff[j] >= 0) ? inp[goff[j]] : 0.f;
            }
            if (tid < 144) s_w[nb][tid] = wp[(ic+1)*9];
        }
        const float* si = s_in[buf];
        const float* sw = s_w[buf];
        #pragma unroll
        for (int dr=0;dr<3;dr++){
            #pragma unroll
            for (int dc=0;dc<3;dc++){
                int kk = dr*3+dc;
                float v0 = si[(ly   +dr)*34 + lx+dc];
                float v1 = si[(ly+ 8+dr)*34 + lx+dc];
                float v2 = si[(ly+16+dr)*34 + lx+dc];
                float v3 = si[(ly+24+dr)*34 + lx+dc];
                #pragma unroll
                for (int o=0;o<16;o++){
                    float wv = sw[o*9+kk];
                    acc[0][o] = fmaf(v0,wv,acc[0][o]);
                    acc[1][o] = fmaf(v1,wv,acc[1][o]);
                    acc[2][o] = fmaf(v2,wv,acc[2][o]);
                    acc[3][o] = fmaf(v3,wv,acc[3][o]);
                }
            }
        }
        __syncthreads();
    }

    #pragma unroll
    for (int o=0;o<16;o++){
        int oc = oc0 + o;
        float bv = bias[oc];
        #pragma unroll
        for (int p=0;p<4;p++){
            float r = fmaxf(acc[p][o] + bv, 0.f);
            out[((size_t)(b*F_+oc)*H_ + (y0+ly+p*8))*W_ + x0+lx] = r;
        }
    }
}

// ---------------- generic dual-network 3x3 conv (layer 3 only) ----------------
__global__ void __launch_bounds__(256, 4) conv3x3_dual(
    const float* __restrict__ inA, const float* __restrict__ wA,
    const float* __restrict__ bA, float* __restrict__ outA, int CoutA,
    const float* __restrict__ inB, const float* __restrict__ wB,
    const float* __restrict__ bB, float* __restrict__ outB, int CoutB,
    int Cin, int relu, int gA)
{
    __shared__ float s_in[34][34];
    __shared__ float s_w[8][9];
    int b   = blockIdx.z;
    int ocg = blockIdx.y;
    const float* in; const float* wgt; const float* bias; float* out; int Cout;
    if (ocg < gA){ in=inA; wgt=wA; bias=bA; out=outA; Cout=CoutA; }
    else { ocg -= gA; in=inB; wgt=wB; bias=bB; out=outB; Cout=CoutB; }

    int tile = blockIdx.x;
    int tx = tile % 7, ty = tile / 7;
    int x0 = tx*32, y0 = ty*32;
    int lx = threadIdx.x, ly = threadIdx.y;
    int tid = ly*32 + lx;

    float acc[4][8];
    #pragma unroll
    for (int p=0;p<4;p++)
        #pragma unroll
        for (int o=0;o<8;o++) acc[p][o]=0.f;

    for (int ic=0; ic<Cin; ic++){
        const float* inp = in + ((size_t)(b*Cin + ic))*H_*W_;
        for (int i=tid; i<34*34; i+=256){
            int r = i/34, c = i%34;
            int gr = y0-1+r, gc = x0-1+c;
            float v = 0.f;
            if (gr>=0 && gr<H_ && gc>=0 && gc<W_) v = inp[gr*W_+gc];
            s_in[r][c] = v;
        }
        if (tid < 72){
            int o = tid/9, kk = tid%9;
            int oc = ocg*8+o;
            s_w[o][kk] = (oc<Cout) ? wgt[(oc*Cin+ic)*9 + kk] : 0.f;
        }
        __syncthreads();

        #pragma unroll
        for (int dr=0;dr<3;dr++){
            #pragma unroll
            for (int dc=0;dc<3;dc++){
                float v0 = s_in[ly     +dr][lx+dc];
                float v1 = s_in[ly+ 8  +dr][lx+dc];
                float v2 = s_in[ly+16  +dr][lx+dc];
                float v3 = s_in[ly+24  +dr][lx+dc];
                int kk = dr*3+dc;
                #pragma unroll
                for (int o=0;o<8;o++){
                    float wv = s_w[o][kk];
                    acc[0][o] = fmaf(v0, wv, acc[0][o]);
                    acc[1][o] = fmaf(v1, wv, acc[1][o]);
                    acc[2][o] = fmaf(v2, wv, acc[2][o]);
                    acc[3][o] = fmaf(v3, wv, acc[3][o]);
                }
            }
        }
        __syncthreads();
    }

    #pragma unroll
    for (int o=0;o<8;o++){
        int oc = ocg*8+o;
        if (oc<Cout){
            float bv = bias[oc];
            #pragma unroll
            for (int p=0;p<4;p++){
                float r = acc[p][o] + bv;
                if (relu) r = fmaxf(r, 0.f);
                out[((size_t)(b*Cout+oc)*H_ + (y0+ly+p*8))*W_ + x0+lx] = r;
            }
        }
    }
}

// ---------------- patch extraction: pe, ||pe||^2, mean log-temp ----------------
__global__ void patches_kernel()
{
    int bn = blockIdx.x;
    int b = bn / N_, n = bn % N_;
    int n1 = n / N1_, n2 = n % N1_;
    int r0 = n1*S_, c0 = n2*S_;
    int tid = threadIdx.x;   // 128

    float loc = 0.f;
    for (int d=tid; d<D_; d+=128){
        int c = d/100, rem = d%100, p1 = rem/10, p2 = rem%10;
        float v = g_xe[((b*E_+c)*H_ + r0+p1)*W_ + c0+p2];
        g_pe[(size_t)bn*D_ + d] = v;
        loc += v*v;
    }
    float lv = 0.f;
    if (tid < 100){
        int p1 = tid/10, p2 = tid%10;
        lv = g_ltmap[(b*H_ + r0+p1)*W_ + c0+p2];
    }
    __shared__ float r1s[4], r2s[4];
    int lane = tid & 31, wid = tid >> 5;
    #pragma unroll
    for (int off=16; off; off>>=1){
        loc += __shfl_xor_sync(0xffffffffu, loc, off);
        lv  += __shfl_xor_sync(0xffffffffu, lv,  off);
    }
    if (lane==0){ r1s[wid]=loc; r2s[wid]=lv; }
    __syncthreads();
    if (tid==0){
        g_sq[bn]  = r1s[0]+r1s[1]+r1s[2]+r1s[3];
        g_ltm[bn] = (r2s[0]+r2s[1]+r2s[2]+r2s[3]) * (1.f/100.f);
    }
}

// ------- fused: distances -> logits -> K iterative softmax -> aggregation -------
__global__ void __launch_bounds__(256) nnblock_kernel(const float* __restrict__ x)
{
    extern __shared__ float sm[];
    float* s_xf = sm;                 // 8 * 40 * 40 = 12800 floats
    float* s_q  = sm + 12800;         // 800 floats
    __shared__ float s_wk[M_][8];
    __shared__ float s_logit[M_];
    __shared__ int   s_cand[M_];
    __shared__ int   s_off[M_];

    int bn = blockIdx.x;
    int b = bn / N_, n = bn % N_;
    int q1 = n / N1_, q2 = n % N1_;
    int tid = threadIdx.x, lane = tid & 31, wid = tid >> 5;

    int c1lo = max(q1-3,0), c1hi = min(q1+3, N1_-1);
    int c2lo = max(q2-3,0), c2hi = min(q2+3, N1_-1);
    int rows = (c1hi-c1lo)*S_ + P_;
    int cols = (c2hi-c2lo)*S_ + P_;
    int r0 = c1lo*S_, c0 = c2lo*S_;

    if (tid < M_){
        int i = tid/7, j = tid%7;
        int c1 = min(max(q1+i-3,0), N1_-1);
        int c2 = min(max(q2+j-3,0), N1_-1);
        s_cand[tid] = c1*N1_ + c2;
        s_off[tid]  = ((c1-c1lo)*S_)*40 + (c2-c2lo)*S_;
    }
    for (int d=tid; d<D_; d+=256) s_q[d] = g_pe[(size_t)bn*D_ + d];

    #pragma unroll
    for (int c=0;c<CIN_;c++){
        const float* src = x + ((size_t)(b*CIN_+c)*H_ + r0)*W_ + c0;
        for (int r=wid; r<rows; r+=8)
            for (int cc=lane; cc<cols; cc+=32)
                s_xf[c*1600 + r*40 + cc] = src[r*W_ + cc];
    }
    __syncthreads();

    float sq_q  = g_sq[bn];
    float scale = expf(-g_ltm[bn]);

    for (int m=wid; m<M_; m+=8){
        int cand = s_cand[m];
        const float* pc = g_pe + (size_t)(b*N_+cand)*D_;
        float s = 0.f;
        for (int j=lane; j<D_; j+=32) s += s_q[j]*pc[j];
        #pragma unroll
        for (int off=16; off; off>>=1) s += __shfl_xor_sync(0xffffffffu, s, off);
        if (lane==0){
            float Dv = -(sq_q + g_sq[b*N_+cand] - 2.f*s);
            s_logit[m] = (cand==n) ? -1e9f : Dv*scale;
        }
    }
    __syncthreads();

    if (tid < 32){
        float a = s_logit[tid];
        bool hasb = (tid+32) < M_;
        float bvl = hasb ? s_logit[tid+32] : -INFINITY;
        #pragma unroll
        for (int k=0;k<K_;k++){
            float mx = fmaxf(a, bvl);
            #pragma unroll
            for (int off=16; off; off>>=1) mx = fmaxf(mx, __shfl_xor_sync(0xffffffffu, mx, off));
            float ea = expf(a - mx);
            float eb = hasb ? expf(bvl - mx) : 0.f;
            float ssum = ea + eb;
            #pragma unroll
            for (int off=16; off; off>>=1) ssum += __shfl_xor_sync(0xffffffffu, ssum, off);
            float inv = 1.f/ssum;
            float wa = ea*inv, wb = eb*inv;
            s_wk[tid][k] = wa;
            if (hasb) s_wk[tid+32][k] = wb;
            a   += log1pf(-fminf(wa, 1.f-1e-6f));
            bvl += log1pf(-fminf(wb, 1.f-1e-6f));
        }
    }
    __syncthreads();

    int baseidx[4]; bool act[4];
    #pragma unroll
    for (int j=0;j<4;j++){
        int d = tid + 256*j;
        act[j] = (d < D_);
        int dd = act[j] ? d : 0;
        int c = dd/100, rem = dd%100, p1 = rem/10, p2 = rem%10;
        baseidx[j] = c*1600 + p1*40 + p2;
    }
    float acc[4][K_];
    #pragma unroll
    for (int j=0;j<4;j++)
        #pragma unroll
        for (int k=0;k<K_;k++) acc[j][k]=0.f;

    for (int m=0;m<M_;m++){
        int o = s_off[m];
        float4 w0 = *(const float4*)&s_wk[m][0];
        float4 w1 = *(const float4*)&s_wk[m][4];
        float v[4];
        #pragma unroll
        for (int j=0;j<4;j++) v[j] = s_xf[baseidx[j]+o];
        #pragma unroll
        for (int j=0;j<4;j++){
            acc[j][0] = fmaf(w0.x, v[j], acc[j][0]);
            acc[j][1] = fmaf(w0.y, v[j], acc[j][1]);
            acc[j][2] = fmaf(w0.z, v[j], acc[j][2]);
            acc[j][3] = fmaf(w0.w, v[j], acc[j][3]);
            acc[j][4] = fmaf(w1.x, v[j], acc[j][4]);
            acc[j][5] = fmaf(w1.y, v[j], acc[j][5]);
            acc[j][6] = fmaf(w1.z, v[j], acc[j][6]);
        }
    }
    #pragma unroll
    for (int j=0;j<4;j++){
        if (!act[j]) continue;
        int d = tid + 256*j;
        #pragma unroll
        for (int k=0;k<K_;k++)
            g_nb[((size_t)(k*B_+b)*N_ + n)*D_ + d] = acc[j][k];
    }
}

// ---------------- gather fold + x passthrough + normalization ----------------
__global__ void fold_kernel(const float* __restrict__ x, float* __restrict__ out)
{
    int idx = blockIdx.x*blockDim.x + threadIdx.x;
    const int total = B_*(K_+1)*CIN_*H_*W_;
    if (idx >= total) return;
    int w  = idx % W_;
    int r  = (idx / W_) % H_;
    int ch = (idx / (H_*W_)) % ((K_+1)*CIN_);
    int b  = idx / (H_*W_*(K_+1)*CIN_);

    if (ch < CIN_){
        out[idx] = x[((b*CIN_+ch)*H_+r)*W_+w];
        return;
    }
    int k = (ch - CIN_) / CIN_;
    int c = (ch - CIN_) % CIN_;

    int n1lo = (r >= P_-1) ? (r-(P_-1)+S_-1)/S_ : 0;
    int n1hi = min(N1_-1, r/S_);
    int n2lo = (w >= P_-1) ? (w-(P_-1)+S_-1)/S_ : 0;
    int n2hi = min(N1_-1, w/S_);

    float sum = 0.f; int cnt = 0;
    for (int n1=n1lo; n1<=n1hi; n1++){
        int p1 = r - n1*S_;
        for (int n2=n2lo; n2<=n2hi; n2++){
            int p2 = w - n2*S_;
            sum += g_nb[((size_t)(k*B_+b)*N_ + n1*N1_+n2)*D_ + c*100 + p1*10 + p2];
            cnt++;
        }
    }
    out[idx] = (cnt > 0) ? sum/(float)cnt : 0.f;
}

// ---------------- launch ----------------
extern "C" void kernel_launch(void* const* d_in, const int* in_sizes, int n_in,
                              void* d_out, int out_size)
{
    const float* x   = (const float*)d_in[0];
    const float* w1e = (const float*)d_in[1];
    const float* b1e = (const float*)d_in[2];
    const float* w2e = (const float*)d_in[3];
    const float* b2e = (const float*)d_in[4];
    const float* w3e = (const float*)d_in[5];
    const float* b3e = (const float*)d_in[6];
    const float* w1t = (const float*)d_in[7];
    const float* b1t = (const float*)d_in[8];
    const float* w2t = (const float*)d_in[9];
    const float* b2t = (const float*)d_in[10];
    const float* w3t = (const float*)d_in[11];
    const float* b3t = (const float*)d_in[12];

    float *t1e, *t1t, *t2e, *t2t, *xe, *ltmap;
    cudaGetSymbolAddress((void**)&t1e,   g_t1e);
    cudaGetSymbolAddress((void**)&t1t,   g_t1t);
    cudaGetSymbolAddress((void**)&t2e,   g_t2e);
    cudaGetSymbolAddress((void**)&t2t,   g_t2t);
    cudaGetSymbolAddress((void**)&xe,    g_xe);
    cudaGetSymbolAddress((void**)&ltmap, g_ltmap);

    static int attr_done = 0;
    if (!attr_done){
        cudaFuncSetAttribute(nnblock_kernel,
                             cudaFuncAttributeMaxDynamicSharedMemorySize, 56*1024);
        attr_done = 1;
    }

    // layer 1: fused over both networks (shared input staging)
    conv1_fused<<<dim3(49,8,B_), 256>>>(x, w1e, b1e, t1e, w1t, b1t, t1t);
    // layer 2: specialized 64->64, 16 oc/block, double-buffered
    conv64x64<<<dim3(49,8,B_), 256>>>(t1e, w2e, b2e, t2e, t1t, w2t, b2t, t2t);
    // layer 3: 8-ch embedding + 1-ch log-temp
    conv3x3_dual<<<dim3(49,2,B_), dim3(32,8)>>>(t2e, w3e, b3e, xe,    E_,
                                                t2t, w3t, b3t, ltmap, 1, F_, 0, 1);

    patches_kernel<<<B_*N_, 128>>>();
    nnblock_kernel<<<B_*N_, 256, (12800+800)*sizeof(float)>>>(x);

    const int total = B_*(K_+1)*CIN_*H_*W_;
    fold_kernel<<<(total+255)/256, 256>>>(x, (float*)d_out);
}